// round 12
// baseline (speedup 1.0000x reference)
#include <cuda_runtime.h>

// Soft-argmax: input (B=4, C=14, H=1024, W=1024) fp32 NCHW.
// Output (4, 2, 1024, 1024) fp32.
//
// R10 (resubmit after infra failure): R5 body + (a) 128-thread CTAs at
// 12 CTAs/SM -> half the CTA lifetime, smaller drain tail; (b) software
// pipeline: group-1 loads issue before group-0's store so the second
// latency chunk overlaps compute.

#define HW      (1024 * 1024)
#define HWQ     (HW / 4)          // 262144 = 2^18 quads per plane
#define HWQ_LOG 18
#define C_IN    14
#define K       7
#define B       4

__device__ __forceinline__ float soft1(float a0, float a1, float a2, float a3,
                                       float a4, float a5, float a6) {
    float e0 = __expf(a0);
    float e1 = __expf(a1);
    float e2 = __expf(a2);
    float e3 = __expf(a3);
    float e4 = __expf(a4);
    float e5 = __expf(a5);
    float e6 = __expf(a6);
    float den = ((e0 + e1) + (e2 + e3)) + ((e4 + e5) + e6);
    float pos = fmaf(3.0f, e6, fmaf(2.0f, e5, e4));
    float neg = fmaf(3.0f, e0, fmaf(2.0f, e1, e2));
    return __fdividef(pos - neg, den);
}

__device__ __forceinline__ float4 compute7(const float4* v) {
    const float* f = reinterpret_cast<const float*>(v);  // f[c*4 + lane]
    float4 r;
    float* o = reinterpret_cast<float*>(&r);
#pragma unroll
    for (int l = 0; l < 4; l++) {
        o[l] = soft1(f[0*4+l], f[1*4+l], f[2*4+l], f[3*4+l],
                     f[4*4+l], f[5*4+l], f[6*4+l]);
    }
    return r;
}

__global__ __launch_bounds__(128, 12)
void softargmax_kernel(const float4* __restrict__ x, float4* __restrict__ out) {
    int q = blockIdx.x * blockDim.x + threadIdx.x;   // [0, B*HWQ)
    int b = q >> HWQ_LOG;
    int s = q & (HWQ - 1);

    const float4* in = x + (size_t)b * C_IN * HWQ + s;
    float4* ob = out + (size_t)b * 2 * HWQ + s;

    // Group 0 loads (channels 0..6)
    float4 v0[K];
#pragma unroll
    for (int c = 0; c < K; c++) {
        v0[c] = __ldcs(&in[(size_t)c * HWQ]);
    }

    // Compute group 0 while nothing else is pending
    float4 r0 = compute7(v0);

    // Group 1 loads (channels 7..13) — issue BEFORE the group-0 store so this
    // latency chunk overlaps the store and the group-1 compute setup.
    float4 v1[K];
#pragma unroll
    for (int c = 0; c < K; c++) {
        v1[c] = __ldcs(&in[(size_t)(K + c) * HWQ]);
    }

    __stcs(&ob[0], r0);

    float4 r1 = compute7(v1);
    __stcs(&ob[HWQ], r1);
}

extern "C" void kernel_launch(void* const* d_in, const int* in_sizes, int n_in,
                              void* d_out, int out_size) {
    const float4* x = (const float4*)d_in[0];
    float4* out = (float4*)d_out;

    const int total_quads = B * HWQ;          // 1,048,576
    const int threads = 128;
    const int blocks = total_quads / threads; // 8192

    softargmax_kernel<<<blocks, threads>>>(x, out);
}